// round 15
// baseline (speedup 1.0000x reference)
#include <cuda_runtime.h>
#include <cstdint>
#include <cstddef>

#define NTOK 131072
constexpr size_t NT = (size_t)NTOK;
constexpr size_t OFF_XW    = 0;
constexpr size_t OFF_T     = NT * 256;
constexpr size_t OFF_QKV   = NT * 512;
constexpr size_t OFF_ATTNO = NT * 1280;
constexpr size_t OFF_XW2   = NT * 1536;
constexpr size_t OFF_F     = NT * 1792;
constexpr size_t OFF_H     = NT * 2048;
constexpr size_t OFF_BT_QKV = NT * 3072;           // 768x256
constexpr size_t OFF_BT_OUT = OFF_BT_QKV + 196608; // 256x256
constexpr size_t OFF_BT_W1  = OFF_BT_OUT + 65536;  // 1024x256
constexpr size_t OFF_BT_W2  = OFF_BT_W1 + 262144;  // 256x1024
__device__ float g_scratch[OFF_BT_W2 + 262144];

__device__ __forceinline__ float rndt(float x) {   // round to tf32, keep as fp32
    uint32_t u; asm("cvt.rna.tf32.f32 %0, %1;" : "=r"(u) : "f"(x));
    return __uint_as_float(u);
}
__device__ __forceinline__ uint32_t smem_u32(const void* p) {
    uint32_t a;
    asm("{.reg .u64 t; cvta.to.shared.u64 t, %1; cvt.u32.u64 %0, t;}" : "=r"(a) : "l"(p));
    return a;
}
__device__ __forceinline__ void cpa16(uint32_t dst, const float* src) {
    asm volatile("cp.async.ca.shared.global [%0], [%1], 16;" :: "r"(dst), "l"(src));
}
__device__ __forceinline__ void mma8(float* d, const uint32_t* a, const uint32_t* b) {
    asm volatile(
        "mma.sync.aligned.m16n8k8.row.col.f32.tf32.tf32.f32 "
        "{%0,%1,%2,%3},{%4,%5,%6,%7},{%8,%9},{%0,%1,%2,%3};"
        : "+f"(d[0]), "+f"(d[1]), "+f"(d[2]), "+f"(d[3])
        : "r"(a[0]), "r"(a[1]), "r"(a[2]), "r"(a[3]), "r"(b[0]), "r"(b[1]));
}

// ---------------- weight transpose BT[n][k] = round_tf32(B[k][n]) --------
__global__ void __launch_bounds__(256) k_transpose(
    const float* __restrict__ B, float* __restrict__ BT, int K, int N)
{
    __shared__ float t[32][33];
    int kb = blockIdx.y * 32, nb = blockIdx.x * 32;
    int tx = threadIdx.x & 31, ty = threadIdx.x >> 5;
    for (int i = ty; i < 32; i += 8) t[i][tx] = B[(size_t)(kb + i) * N + nb + tx];
    __syncthreads();
    for (int i = ty; i < 32; i += 8) BT[(size_t)(nb + i) * K + kb + tx] = rndt(t[tx][i]);
}

// -------- FUSED gather + LN2(LN1(.)): one block per 8x8 window ----------
// Reads x (NCHW) once; writes XW (raw, residual) and T (double-LN, rounded).
// smem: sx[64][257] + stats; dynamic.
#define GLN_SMEM ((64 * 257 + 256) * 4)
__global__ void __launch_bounds__(256) k_gather_ln(
    const float* __restrict__ x,
    const float* __restrict__ g1, const float* __restrict__ b1,
    const float* __restrict__ g2, const float* __restrict__ b2)
{
    extern __shared__ float sh[];
    float* sx  = sh;                 // [64][257]
    float* st1 = sh + 64 * 257;      // [64][2]
    float* st2 = st1 + 128;          // [64][2]
    __shared__ float sg1[256], sb1[256], sg2[256], sb2[256];

    const int tid = threadIdx.x, w = blockIdx.x;
    const int b = w >> 10, wx = (w >> 5) & 31, wy = w & 31;
    sg1[tid] = g1[tid]; sb1[tid] = b1[tid];
    sg2[tid] = g2[tid]; sb2[tid] = b2[tid];

    // load: thread -> (tok = tid&63, d = it*4 + (tid>>6)); 32B-sector coalesced
    const int tok = tid & 63, dh = tid >> 6;
    const int w1 = tok >> 3, w2 = tok & 7;
    const float* xp = x + (size_t)b * 256 * 65536 + (size_t)dh * 65536
                        + (size_t)(wx * 8 + w1) * 256 + wy * 8 + w2;
#pragma unroll
    for (int it = 0; it < 64; ++it)
        sx[tok * 257 + it * 4 + dh] = xp[(size_t)(it * 4) * 65536];
    __syncthreads();

    // stats: warp handles 8 tokens
    const int warp = tid >> 5, lane = tid & 31;
#pragma unroll
    for (int j = 0; j < 8; ++j) {
        int tk = warp * 8 + j;
        float s = 0.f, ss = 0.f;
#pragma unroll
        for (int m = 0; m < 8; ++m) {
            float v = sx[tk * 257 + lane + 32 * m]; s += v; ss += v * v;
        }
#pragma unroll
        for (int o = 16; o > 0; o >>= 1) {
            s += __shfl_xor_sync(~0u, s, o); ss += __shfl_xor_sync(~0u, ss, o);
        }
        float m1 = s * (1.f / 256.f), i1 = rsqrtf(ss * (1.f / 256.f) - m1 * m1 + 1e-5f);
        if (lane == 0) { st1[tk * 2] = m1; st1[tk * 2 + 1] = i1; }
        float s2 = 0.f, ss2 = 0.f;
#pragma unroll
        for (int m = 0; m < 8; ++m) {
            int d = lane + 32 * m;
            float u = (sx[tk * 257 + d] - m1) * i1 * sg1[d] + sb1[d];
            s2 += u; ss2 += u * u;
        }
#pragma unroll
        for (int o = 16; o > 0; o >>= 1) {
            s2 += __shfl_xor_sync(~0u, s2, o); ss2 += __shfl_xor_sync(~0u, ss2, o);
        }
        if (lane == 0) {
            float m2 = s2 * (1.f / 256.f);
            st2[tk * 2] = m2; st2[tk * 2 + 1] = rsqrtf(ss2 * (1.f / 256.f) - m2 * m2 + 1e-5f);
        }
    }
    __syncthreads();

    const size_t base = (size_t)w * 64 * 256;
    float* XW = g_scratch + OFF_XW + base;
    float* T  = g_scratch + OFF_T + base;
#pragma unroll
    for (int tk = 0; tk < 64; ++tk) {
        float v = sx[tk * 257 + tid];
        float u = (v - st1[tk * 2]) * st1[tk * 2 + 1] * sg1[tid] + sb1[tid];
        u = (u - st2[tk * 2]) * st2[tk * 2 + 1] * sg2[tid] + sb2[tid];
        XW[tk * 256 + tid] = v;
        T[tk * 256 + tid]  = rndt(u);
    }
}

// ---------------- scatter token-major y (OFF_T) -> NCHW ------------------
__global__ void __launch_bounds__(256) k_scatter(float* __restrict__ out)
{
    __shared__ float sm[256][33];
    int tid = threadIdx.x, bi = blockIdx.x;
    int dc = bi & 7, w1 = (bi >> 3) & 7, wx = (bi >> 6) & 31, b = bi >> 11;
#pragma unroll
    for (int it = 0; it < 32; ++it) {
        int t = it * 8 + (tid >> 5), dd = tid & 31;
        size_t tok = (((size_t)b * 32 + wx) * 32 + (t >> 3)) * 64 + w1 * 8 + (t & 7);
        sm[t][dd] = g_scratch[OFF_T + tok * 256 + dc * 32 + dd];
    }
    __syncthreads();
    float* ob = out + ((size_t)b * 256 + dc * 32) * 65536 + (size_t)(wx * 8 + w1) * 256;
#pragma unroll
    for (int it = 0; it < 32; ++it) ob[(size_t)it * 65536 + tid] = sm[tid][it];
}

// ------- single LayerNorm (ln3): reads XW2, writes F (tf32-rounded) ------
__global__ void __launch_bounds__(256) k_ln3(
    const float* __restrict__ src, float* __restrict__ dst,
    const float* __restrict__ g1, const float* __restrict__ b1)
{
    __shared__ float sm[8192], sg1[256], sb1[256], st1[32][2];
    int tid = threadIdx.x;
    size_t base = (size_t)blockIdx.x * 8192;
    sg1[tid] = g1[tid]; sb1[tid] = b1[tid];
#pragma unroll
    for (int it = 0; it < 32; ++it) sm[it * 256 + tid] = src[base + it * 256 + tid];
    __syncthreads();
    int warp = tid >> 5, lane = tid & 31;
#pragma unroll
    for (int j = 0; j < 4; ++j) {
        int tok = warp * 4 + j;
        float s = 0.f, ss = 0.f;
#pragma unroll
        for (int m = 0; m < 8; ++m) {
            float v = sm[tok * 256 + lane + 32 * m]; s += v; ss += v * v;
        }
#pragma unroll
        for (int o = 16; o > 0; o >>= 1) {
            s += __shfl_xor_sync(~0u, s, o); ss += __shfl_xor_sync(~0u, ss, o);
        }
        if (lane == 0) {
            float m1 = s * (1.f / 256.f);
            st1[tok][0] = m1;
            st1[tok][1] = rsqrtf(ss * (1.f / 256.f) - m1 * m1 + 1e-5f);
        }
    }
    __syncthreads();
#pragma unroll
    for (int tok = 0; tok < 32; ++tok) {
        float v = sm[tok * 256 + tid];
        dst[base + tok * 256 + tid] =
            rndt((v - st1[tok][0]) * st1[tok][1] * sg1[tid] + sb1[tid]);
    }
}

// -------- tf32 mma.sync GEMM (R10 config, N/K templated for const-folding)
// 128x128, BK=32, 8 warps (32x64), 2-stage cp.async.ca, 2 CTAs/SM.
// EPI: 0 none | 1 +RES | 2 round(gelu(+BIAS)) | 3 +BIAS+RES
#define GEMM_SMEM 73728
template <int EPI, int N, int K>
__global__ void __launch_bounds__(256, 2) k_gemm_mma(
    const float* __restrict__ A, const float* __restrict__ BT,
    float* __restrict__ C, const float* __restrict__ RES,
    const float* __restrict__ BIAS)
{
    extern __shared__ float smf[];   // 2 stages x (A[128][36] + B[128][36])
    const int tid = threadIdx.x, lane = tid & 31, wid = tid >> 5;
    const int bm = blockIdx.y << 7, bn = blockIdx.x << 7;
    const int wr = wid & 3, wc = wid >> 2;
    const int g = lane >> 2, q = lane & 3;

    const int lrow = tid >> 3, lkq = (tid & 7) << 2;
    const float* ApG = A  + (size_t)(bm + lrow) * K + lkq;
    const float* BpG = BT + (size_t)(bn + lrow) * K + lkq;
    const uint32_t sBase = smem_u32(smf);
    const uint32_t soff = ((uint32_t)lrow * 36 + (uint32_t)lkq) * 4;

    float acc[2][8][4];
#pragma unroll
    for (int i = 0; i < 2; ++i)
#pragma unroll
        for (int j = 0; j < 8; ++j)
#pragma unroll
            for (int e = 0; e < 4; ++e) acc[i][j][e] = 0.f;

#pragma unroll
    for (int it = 0; it < 4; ++it) {
        cpa16(sBase + soff + it * 32 * 36 * 4, ApG + (size_t)(it * 32) * K);
        cpa16(sBase + 18432u + soff + it * 32 * 36 * 4, BpG + (size_t)(it * 32) * K);
    }
    asm volatile("cp.async.commit_group;" ::: "memory");

    constexpr int nc = K >> 5;
#pragma unroll 2
    for (int c = 0; c < nc; ++c) {
        if (c + 1 < nc) {
            const int kc = (c + 1) << 5;
            const uint32_t st = sBase + (uint32_t)((c + 1) & 1) * 36864u;
#pragma unroll
            for (int it = 0; it < 4; ++it) {
                cpa16(st + soff + it * 32 * 36 * 4, ApG + (size_t)(it * 32) * K + kc);
                cpa16(st + 18432u + soff + it * 32 * 36 * 4, BpG + (size_t)(it * 32) * K + kc);
            }
            asm volatile("cp.async.commit_group;" ::: "memory");
            asm volatile("cp.async.wait_group 1;" ::: "memory");
        } else {
            asm volatile("cp.async.wait_group 0;" ::: "memory");
        }
        __syncthreads();

        const uint32_t* Ab = (const uint32_t*)(smf + (c & 1) * 9216) + (wr << 5) * 36;
        const uint32_t* Bb = (const uint32_t*)(smf + (c & 1) * 9216 + 4608) + (wc << 6) * 36;
#pragma unroll
        for (int ks = 0; ks < 4; ++ks) {
            const int kb = ks << 3;
            uint32_t af[2][4];
#pragma unroll
            for (int mt = 0; mt < 2; ++mt) {
                af[mt][0] = Ab[(mt * 16 + g) * 36 + kb + q];
                af[mt][1] = Ab[(mt * 16 + 8 + g) * 36 + kb + q];
                af[mt][2] = Ab[(mt * 16 + g) * 36 + kb + 4 + q];
                af[mt][3] = Ab[(mt * 16 + 8 + g) * 36 + kb + 4 + q];
            }
#pragma unroll
            for (int nt = 0; nt < 8; ++nt) {
                uint32_t bf[2];
                bf[0] = Bb[(nt * 8 + g) * 36 + kb + q];
                bf[1] = Bb[(nt * 8 + g) * 36 + kb + 4 + q];
                mma8(acc[0][nt], af[0], bf);
                mma8(acc[1][nt], af[1], bf);
            }
        }
        __syncthreads();
    }

#pragma unroll
    for (int mt = 0; mt < 2; ++mt) {
#pragma unroll
        for (int nt = 0; nt < 8; ++nt) {
            int row0 = bm + (wr << 5) + mt * 16 + g;
            int col  = bn + (wc << 6) + nt * 8 + q * 2;
            float v00 = acc[mt][nt][0], v01 = acc[mt][nt][1];
            float v10 = acc[mt][nt][2], v11 = acc[mt][nt][3];
            if (EPI == 2 || EPI == 3) {
                float2 bb = *(const float2*)(BIAS + col);
                v00 += bb.x; v01 += bb.y; v10 += bb.x; v11 += bb.y;
            }
            if (EPI == 1 || EPI == 3) {
                float2 r0 = *(const float2*)(RES + (size_t)row0 * N + col);
                float2 r1 = *(const float2*)(RES + (size_t)(row0 + 8) * N + col);
                v00 += r0.x; v01 += r0.y; v10 += r1.x; v11 += r1.y;
            }
            if (EPI == 2) {
                v00 = rndt(v00 * normcdff(v00)); v01 = rndt(v01 * normcdff(v01));
                v10 = rndt(v10 * normcdff(v10)); v11 = rndt(v11 * normcdff(v11));
            }
            *(float2*)(C + (size_t)row0 * N + col)       = make_float2(v00, v01);
            *(float2*)(C + (size_t)(row0 + 8) * N + col) = make_float2(v10, v11);
        }
    }
}

// -------- windowed attention via mma.sync (R14, unchanged) ---------------
#define ATTN_SMEM 96288
__global__ void __launch_bounds__(256) k_attn(const float* __restrict__ rpb)
{
    extern __shared__ float sa[];
    float* sQ  = sa;            // [lh*2304 + t*36 + d]
    float* sK  = sa + 4608;     // [lh*2304 + t*36 + d]
    float* sVt = sa + 9216;     // [lh*2176 + d*68 + t]
    float* sP  = sa + 13568;    // [lh*4352 + r*68 + c]
    float* srpb = sa + 22272;   // [1800]

    const int tid = threadIdx.x, lane = tid & 31, wid = tid >> 5;
    const int g = lane >> 2, q = lane & 3;
    const int hh = wid >> 2, slice = (wid & 3) << 4;
    const size_t tokbase = (size_t)blockIdx.x * 64;
    const float* qkv = g_scratch + OFF_QKV;
    float* outp = g_scratch + OFF_ATTNO;
    for (int i = tid; i < 1800; i += 256) srpb[i] = rpb[i];
    const float sc = 0.17677669529663687f;

    for (int h = 0; h < 8; h += 2) {
        __syncthreads();
#pragma unroll
        for (int m = 0; m < 4; ++m) {
            int e = m * 256 + tid;
            int t = e >> 4, rem = e & 15;
            int lh = rem >> 3, d4 = (rem & 7) << 2;
            const float* src = qkv + (tokbase + t) * 768 + (h + lh) * 32 + d4;
            float4 q4 = *(const float4*)src;
            float4 k4 = *(const float4*)(src + 256);
            float4 v4 = *(const float4*)(src + 512);
            float* dq = sQ + lh * 2304 + t * 36 + d4;
            dq[0] = rndt(q4.x * sc); dq[1] = rndt(q4.y * sc);
            dq[2] = rndt(q4.z * sc); dq[3] = rndt(q4.w * sc);
            float* dk = sK + lh * 2304 + t * 36 + d4;
            dk[0] = rndt(k4.x); dk[1] = rndt(k4.y);
            dk[2] = rndt(k4.z); dk[3] = rndt(k4.w);
            float* dv = sVt + lh * 2176 + t;
            dv[(d4 + 0) * 68] = rndt(v4.x); dv[(d4 + 1) * 68] = rndt(v4.y);
            dv[(d4 + 2) * 68] = rndt(v4.z); dv[(d4 + 3) * 68] = rndt(v4.w);
        }
        __syncthreads();

        const float* Q = sQ + hh * 2304;
        const float* K = sK + hh * 2304;
        float accs[8][4];
#pragma unroll
        for (int nt = 0; nt < 8; ++nt)
#pragma unroll
            for (int e = 0; e < 4; ++e) accs[nt][e] = 0.f;
#pragma unroll
        for (int kt = 0; kt < 4; ++kt) {
            const int kb = kt << 3;
            uint32_t af[4];
            af[0] = __float_as_uint(Q[(slice + g) * 36 + kb + q]);
            af[1] = __float_as_uint(Q[(slice + 8 + g) * 36 + kb + q]);
            af[2] = __float_as_uint(Q[(slice + g) * 36 + kb + 4 + q]);
            af[3] = __float_as_uint(Q[(slice + 8 + g) * 36 + kb + 4 + q]);
#pragma unroll
            for (int nt = 0; nt < 8; ++nt) {
                uint32_t bf[2];
                bf[0] = __float_as_uint(K[(nt * 8 + g) * 36 + kb + q]);
                bf[1] = __float_as_uint(K[(nt * 8 + g) * 36 + kb + 4 + q]);
                mma8(accs[nt], af, bf);
            }
        }

        const int r0 = slice + g, r1 = r0 + 8;
        const int ri0 = r0 >> 3, rj0 = r0 & 7, ri1 = r1 >> 3, rj1 = r1 & 7;
#pragma unroll
        for (int nt = 0; nt < 8; ++nt) {
            int c0 = nt * 8 + 2 * q, c1 = c0 + 1;
            int ci0 = c0 >> 3, cj0 = c0 & 7, ci1 = c1 >> 3, cj1 = c1 & 7;
            accs[nt][0] += srpb[((ri0 - ci0 + 7) * 15 + (rj0 - cj0 + 7)) * 8 + h + hh];
            accs[nt][1] += srpb[((ri0 - ci1 + 7) * 15 + (rj0 - cj1 + 7)) * 8 + h + hh];
            accs[nt][2] += srpb[((ri1 - ci0 + 7) * 15 + (rj1 - cj0 + 7)) * 8 + h + hh];
            accs[nt][3] += srpb[((ri1 - ci1 + 7) * 15 + (rj1 - cj1 + 7)) * 8 + h + hh];
        }

        float mx0 = accs[0][0], mx1 = accs[0][2];
#pragma unroll
        for (int nt = 0; nt < 8; ++nt) {
            mx0 = fmaxf(mx0, fmaxf(accs[nt][0], accs[nt][1]));
            mx1 = fmaxf(mx1, fmaxf(accs[nt][2], accs[nt][3]));
        }
        mx0 = fmaxf(mx0, __shfl_xor_sync(~0u, mx0, 1));
        mx0 = fmaxf(mx0, __shfl_xor_sync(~0u, mx0, 2));
        mx1 = fmaxf(mx1, __shfl_xor_sync(~0u, mx1, 1));
        mx1 = fmaxf(mx1, __shfl_xor_sync(~0u, mx1, 2));
        float sum0 = 0.f, sum1 = 0.f;
#pragma unroll
        for (int nt = 0; nt < 8; ++nt) {
            accs[nt][0] = __expf(accs[nt][0] - mx0); sum0 += accs[nt][0];
            accs[nt][1] = __expf(accs[nt][1] - mx0); sum0 += accs[nt][1];
            accs[nt][2] = __expf(accs[nt][2] - mx1); sum1 += accs[nt][2];
            accs[nt][3] = __expf(accs[nt][3] - mx1); sum1 += accs[nt][3];
        }
        sum0 += __shfl_xor_sync(~0u, sum0, 1); sum0 += __shfl_xor_sync(~0u, sum0, 2);
        sum1 += __shfl_xor_sync(~0u, sum1, 1); sum1 += __shfl_xor_sync(~0u, sum1, 2);
        float inv0 = 1.f / sum0, inv1 = 1.f / sum1;

        float* P = sP + hh * 4352;
#pragma unroll
        for (int nt = 0; nt < 8; ++nt) {
            int c0 = nt * 8 + 2 * q;
            P[r0 * 68 + c0]     = rndt(accs[nt][0] * inv0);
            P[r0 * 68 + c0 + 1] = rndt(accs[nt][1] * inv0);
            P[r1 * 68 + c0]     = rndt(accs[nt][2] * inv1);
            P[r1 * 68 + c0 + 1] = rndt(accs[nt][3] * inv1);
        }
        __syncthreads();

        const float* Vt = sVt + hh * 2176;
        float acco[4][4];
#pragma unroll
        for (int nt = 0; nt < 4; ++nt)
#pragma unroll
            for (int e = 0; e < 4; ++e) acco[nt][e] = 0.f;
#pragma unroll
        for (int kt = 0; kt < 8; ++kt) {
            const int kb = kt << 3;
            uint32_t af[4];
            af[0] = __float_as_uint(P[(slice + g) * 68 + kb + q]);
            af[1] = __float_as_uint(P[(slice + 8 + g) * 68 + kb + q]);
            af[2] = __float_as_uint(P[(slice + g) * 68 + kb + 4 + q]);
            af[3] = __float_as_uint(P[(slice + 8 + g) * 68 + kb + 4 + q]);
#pragma unroll
            for (int nt = 0; nt < 4; ++nt) {
                uint32_t bf[2];
                bf[0] = __float_as_uint(Vt[(nt * 8 + g) * 68 + kb + q]);
                bf[1] = __float_as_uint(Vt[(nt * 8 + g) * 68 + kb + 4 + q]);
                mma8(acco[nt], af, bf);
            }
        }
#pragma unroll
        for (int nt = 0; nt < 4; ++nt) {
            int col = nt * 8 + 2 * q;
            float* d0 = outp + (tokbase + r0) * 256 + (h + hh) * 32 + col;
            float* d1 = outp + (tokbase + r1) * 256 + (h + hh) * 32 + col;
            *(float2*)d0 = make_float2(rndt(acco[nt][0]), rndt(acco[nt][1]));
            *(float2*)d1 = make_float2(rndt(acco[nt][2]), rndt(acco[nt][3]));
        }
    }
}

// ---------------- host launcher ----------------
extern "C" void kernel_launch(void* const* d_in, const int* in_sizes, int n_in,
                              void* d_out, int out_size)
{
    const float* x     = (const float*)d_in[0];
    const float* ln1_g = (const float*)d_in[1];
    const float* ln1_b = (const float*)d_in[2];
    const float* ln2_g = (const float*)d_in[3];
    const float* ln2_b = (const float*)d_in[4];
    const float* w_qkv = (const float*)d_in[5];
    const float* w_out = (const float*)d_in[6];
    const float* rpb   = (const float*)d_in[7];
    const float* ln3_g = (const float*)d_in[8];
    const float* ln3_b = (const float*)d_in[9];
    const float* w1    = (const float*)d_in[10];
    const float* b1    = (const float*)d_in[11];
    const float* w2    = (const float*)d_in[12];
    const float* b2    = (const float*)d_in[13];
    float* out = (float*)d_out;

    float* S = nullptr;
    cudaGetSymbolAddress((void**)&S, g_scratch);

    cudaFuncSetAttribute(k_gemm_mma<0, 768, 256>,  cudaFuncAttributeMaxDynamicSharedMemorySize, GEMM_SMEM);
    cudaFuncSetAttribute(k_gemm_mma<1, 256, 256>,  cudaFuncAttributeMaxDynamicSharedMemorySize, GEMM_SMEM);
    cudaFuncSetAttribute(k_gemm_mma<2, 1024, 256>, cudaFuncAttributeMaxDynamicSharedMemorySize, GEMM_SMEM);
    cudaFuncSetAttribute(k_gemm_mma<3, 256, 1024>, cudaFuncAttributeMaxDynamicSharedMemorySize, GEMM_SMEM);
    cudaFuncSetAttribute(k_attn,      cudaFuncAttributeMaxDynamicSharedMemorySize, ATTN_SMEM);
    cudaFuncSetAttribute(k_gather_ln, cudaFuncAttributeMaxDynamicSharedMemorySize, GLN_SMEM);

    k_gather_ln<<<2048, 256, GLN_SMEM>>>(x, ln1_g, ln1_b, ln2_g, ln2_b);     // 1
    k_transpose<<<dim3(24, 8), 256>>>(w_qkv, S + OFF_BT_QKV, 256, 768);      // 2
    k_transpose<<<dim3(8, 8), 256>>>(w_out, S + OFF_BT_OUT, 256, 256);       // 3
    k_gemm_mma<0, 768, 256><<<dim3(6, 1024), 256, GEMM_SMEM>>>(              // 4 (profiled)
        S + OFF_T, S + OFF_BT_QKV, S + OFF_QKV, S, S);
    k_transpose<<<dim3(32, 8), 256>>>(w1, S + OFF_BT_W1, 256, 1024);         // 5
    k_transpose<<<dim3(8, 32), 256>>>(w2, S + OFF_BT_W2, 1024, 256);         // 6
    k_attn<<<2048, 256, ATTN_SMEM>>>(rpb);                                   // 7
    k_gemm_mma<1, 256, 256><<<dim3(2, 1024), 256, GEMM_SMEM>>>(
        S + OFF_ATTNO, S + OFF_BT_OUT, S + OFF_XW2, S + OFF_XW, S);
    k_ln3<<<4096, 256>>>(S + OFF_XW2, S + OFF_F, ln3_g, ln3_b);
    k_gemm_mma<2, 1024, 256><<<dim3(8, 1024), 256, GEMM_SMEM>>>(
        S + OFF_F, S + OFF_BT_W1, S + OFF_H, S, b1);
    k_gemm_mma<3, 256, 1024><<<dim3(2, 1024), 256, GEMM_SMEM>>>(
        S + OFF_H, S + OFF_BT_W2, S + OFF_T, S + OFF_XW2, b2);
    k_scatter<<<4096, 256>>>(out);
}

// round 16
// speedup vs baseline: 1.0183x; 1.0183x over previous
#include <cuda_runtime.h>
#include <cstdint>
#include <cstddef>

#define NTOK 131072
constexpr size_t NT = (size_t)NTOK;
constexpr size_t OFF_XW    = 0;
constexpr size_t OFF_T     = NT * 256;
constexpr size_t OFF_QKV   = NT * 512;
constexpr size_t OFF_ATTNO = NT * 1280;
constexpr size_t OFF_XW2   = NT * 1536;
constexpr size_t OFF_F     = NT * 1792;
constexpr size_t OFF_H     = NT * 2048;
constexpr size_t OFF_BT_QKV = NT * 3072;           // 768x256
constexpr size_t OFF_BT_OUT = OFF_BT_QKV + 196608; // 256x256
constexpr size_t OFF_BT_W1  = OFF_BT_OUT + 65536;  // 1024x256
constexpr size_t OFF_BT_W2  = OFF_BT_W1 + 262144;  // 256x1024
__device__ float g_scratch[OFF_BT_W2 + 262144];

__device__ __forceinline__ float rndt(float x) {   // round to tf32, keep as fp32
    uint32_t u; asm("cvt.rna.tf32.f32 %0, %1;" : "=r"(u) : "f"(x));
    return __uint_as_float(u);
}
__device__ __forceinline__ uint32_t smem_u32(const void* p) {
    uint32_t a;
    asm("{.reg .u64 t; cvta.to.shared.u64 t, %1; cvt.u32.u64 %0, t;}" : "=r"(a) : "l"(p));
    return a;
}
__device__ __forceinline__ void cpa16(uint32_t dst, const float* src) {
    asm volatile("cp.async.ca.shared.global [%0], [%1], 16;" :: "r"(dst), "l"(src));
}
__device__ __forceinline__ void mma8(float* d, const uint32_t* a, const uint32_t* b) {
    asm volatile(
        "mma.sync.aligned.m16n8k8.row.col.f32.tf32.tf32.f32 "
        "{%0,%1,%2,%3},{%4,%5,%6,%7},{%8,%9},{%0,%1,%2,%3};"
        : "+f"(d[0]), "+f"(d[1]), "+f"(d[2]), "+f"(d[3])
        : "r"(a[0]), "r"(a[1]), "r"(a[2]), "r"(a[3]), "r"(b[0]), "r"(b[1]));
}
// ldmatrix x4 on 32-bit data: per matrix, lane gets elem(row=lane>>2, col=lane&3)
__device__ __forceinline__ void ldsm4(uint32_t* r, uint32_t addr) {
    asm volatile("ldmatrix.sync.aligned.m8n8.x4.shared.b16 {%0,%1,%2,%3}, [%4];"
        : "=r"(r[0]), "=r"(r[1]), "=r"(r[2]), "=r"(r[3]) : "r"(addr));
}

// ---------------- weight transpose BT[n][k] = round_tf32(B[k][n]) --------
__global__ void __launch_bounds__(256) k_transpose(
    const float* __restrict__ B, float* __restrict__ BT, int K, int N)
{
    __shared__ float t[32][33];
    int kb = blockIdx.y * 32, nb = blockIdx.x * 32;
    int tx = threadIdx.x & 31, ty = threadIdx.x >> 5;
    for (int i = ty; i < 32; i += 8) t[i][tx] = B[(size_t)(kb + i) * N + nb + tx];
    __syncthreads();
    for (int i = ty; i < 32; i += 8) BT[(size_t)(nb + i) * K + kb + tx] = rndt(t[tx][i]);
}

// -------- FUSED gather + LN2(LN1(.)): one block per 8x8 window ----------
#define GLN_SMEM ((64 * 257 + 256) * 4)
__global__ void __launch_bounds__(256) k_gather_ln(
    const float* __restrict__ x,
    const float* __restrict__ g1, const float* __restrict__ b1,
    const float* __restrict__ g2, const float* __restrict__ b2)
{
    extern __shared__ float sh[];
    float* sx  = sh;                 // [64][257]
    float* st1 = sh + 64 * 257;      // [64][2]
    float* st2 = st1 + 128;          // [64][2]
    __shared__ float sg1[256], sb1[256], sg2[256], sb2[256];

    const int tid = threadIdx.x, w = blockIdx.x;
    const int b = w >> 10, wx = (w >> 5) & 31, wy = w & 31;
    sg1[tid] = g1[tid]; sb1[tid] = b1[tid];
    sg2[tid] = g2[tid]; sb2[tid] = b2[tid];

    const int tok = tid & 63, dh = tid >> 6;
    const int w1 = tok >> 3, w2 = tok & 7;
    const float* xp = x + (size_t)b * 256 * 65536 + (size_t)dh * 65536
                        + (size_t)(wx * 8 + w1) * 256 + wy * 8 + w2;
#pragma unroll
    for (int it = 0; it < 64; ++it)
        sx[tok * 257 + it * 4 + dh] = xp[(size_t)(it * 4) * 65536];
    __syncthreads();

    const int warp = tid >> 5, lane = tid & 31;
#pragma unroll
    for (int j = 0; j < 8; ++j) {
        int tk = warp * 8 + j;
        float s = 0.f, ss = 0.f;
#pragma unroll
        for (int m = 0; m < 8; ++m) {
            float v = sx[tk * 257 + lane + 32 * m]; s += v; ss += v * v;
        }
#pragma unroll
        for (int o = 16; o > 0; o >>= 1) {
            s += __shfl_xor_sync(~0u, s, o); ss += __shfl_xor_sync(~0u, ss, o);
        }
        float m1 = s * (1.f / 256.f), i1 = rsqrtf(ss * (1.f / 256.f) - m1 * m1 + 1e-5f);
        if (lane == 0) { st1[tk * 2] = m1; st1[tk * 2 + 1] = i1; }
        float s2 = 0.f, ss2 = 0.f;
#pragma unroll
        for (int m = 0; m < 8; ++m) {
            int d = lane + 32 * m;
            float u = (sx[tk * 257 + d] - m1) * i1 * sg1[d] + sb1[d];
            s2 += u; ss2 += u * u;
        }
#pragma unroll
        for (int o = 16; o > 0; o >>= 1) {
            s2 += __shfl_xor_sync(~0u, s2, o); ss2 += __shfl_xor_sync(~0u, ss2, o);
        }
        if (lane == 0) {
            float m2 = s2 * (1.f / 256.f);
            st2[tk * 2] = m2; st2[tk * 2 + 1] = rsqrtf(ss2 * (1.f / 256.f) - m2 * m2 + 1e-5f);
        }
    }
    __syncthreads();

    const size_t base = (size_t)w * 64 * 256;
    float* XW = g_scratch + OFF_XW + base;
    float* T  = g_scratch + OFF_T + base;
#pragma unroll
    for (int tk = 0; tk < 64; ++tk) {
        float v = sx[tk * 257 + tid];
        float u = (v - st1[tk * 2]) * st1[tk * 2 + 1] * sg1[tid] + sb1[tid];
        u = (u - st2[tk * 2]) * st2[tk * 2 + 1] * sg2[tid] + sb2[tid];
        XW[tk * 256 + tid] = v;
        T[tk * 256 + tid]  = rndt(u);
    }
}

// ---------------- scatter token-major y (OFF_T) -> NCHW ------------------
__global__ void __launch_bounds__(256) k_scatter(float* __restrict__ out)
{
    __shared__ float sm[256][33];
    int tid = threadIdx.x, bi = blockIdx.x;
    int dc = bi & 7, w1 = (bi >> 3) & 7, wx = (bi >> 6) & 31, b = bi >> 11;
#pragma unroll
    for (int it = 0; it < 32; ++it) {
        int t = it * 8 + (tid >> 5), dd = tid & 31;
        size_t tok = (((size_t)b * 32 + wx) * 32 + (t >> 3)) * 64 + w1 * 8 + (t & 7);
        sm[t][dd] = g_scratch[OFF_T + tok * 256 + dc * 32 + dd];
    }
    __syncthreads();
    float* ob = out + ((size_t)b * 256 + dc * 32) * 65536 + (size_t)(wx * 8 + w1) * 256;
#pragma unroll
    for (int it = 0; it < 32; ++it) ob[(size_t)it * 65536 + tid] = sm[tid][it];
}

// ------- single LayerNorm (ln3): reads XW2, writes F (tf32-rounded) ------
__global__ void __launch_bounds__(256) k_ln3(
    const float* __restrict__ src, float* __restrict__ dst,
    const float* __restrict__ g1, const float* __restrict__ b1)
{
    __shared__ float sm[8192], sg1[256], sb1[256], st1[32][2];
    int tid = threadIdx.x;
    size_t base = (size_t)blockIdx.x * 8192;
    sg1[tid] = g1[tid]; sb1[tid] = b1[tid];
#pragma unroll
    for (int it = 0; it < 32; ++it) sm[it * 256 + tid] = src[base + it * 256 + tid];
    __syncthreads();
    int warp = tid >> 5, lane = tid & 31;
#pragma unroll
    for (int j = 0; j < 4; ++j) {
        int tok = warp * 4 + j;
        float s = 0.f, ss = 0.f;
#pragma unroll
        for (int m = 0; m < 8; ++m) {
            float v = sm[tok * 256 + lane + 32 * m]; s += v; ss += v * v;
        }
#pragma unroll
        for (int o = 16; o > 0; o >>= 1) {
            s += __shfl_xor_sync(~0u, s, o); ss += __shfl_xor_sync(~0u, ss, o);
        }
        if (lane == 0) {
            float m1 = s * (1.f / 256.f);
            st1[tok][0] = m1;
            st1[tok][1] = rsqrtf(ss * (1.f / 256.f) - m1 * m1 + 1e-5f);
        }
    }
    __syncthreads();
#pragma unroll
    for (int tok = 0; tok < 32; ++tok) {
        float v = sm[tok * 256 + tid];
        dst[base + tok * 256 + tid] =
            rndt((v - st1[tok][0]) * st1[tok][1] * sg1[tid] + sb1[tid]);
    }
}

// -------- tf32 mma.sync GEMM with ldmatrix fragment loads ---------------
// 128x128, BK=32, 8 warps (32x64), 2-stage cp.async.ca, 2 CTAs/SM.
// Fragment loads: ldmatrix.x4 (A: 1/mt; B: 1 per nt-pair) -> 6 LDSM/ks.
// EPI: 0 none | 1 +RES | 2 round(gelu(+BIAS)) | 3 +BIAS+RES
#define GEMM_SMEM 73728
template <int EPI, int N, int K>
__global__ void __launch_bounds__(256, 2) k_gemm_mma(
    const float* __restrict__ A, const float* __restrict__ BT,
    float* __restrict__ C, const float* __restrict__ RES,
    const float* __restrict__ BIAS)
{
    extern __shared__ float smf[];   // 2 stages x (A[128][36] + B[128][36])
    const int tid = threadIdx.x, lane = tid & 31, wid = tid >> 5;
    const int bm = blockIdx.y << 7, bn = blockIdx.x << 7;
    const int wr = wid & 3, wc = wid >> 2;
    const int g = lane >> 2, q = lane & 3;

    const int lrow = tid >> 3, lkq = (tid & 7) << 2;
    const float* ApG = A  + (size_t)(bm + lrow) * K + lkq;
    const float* BpG = BT + (size_t)(bn + lrow) * K + lkq;
    const uint32_t sBase = smem_u32(smf);
    const uint32_t soff = ((uint32_t)lrow * 36 + (uint32_t)lkq) * 4;

    // ldmatrix per-lane offset (bytes): matrices = {rows+0,rows+8} x {col 0,+4}
    const int ls = lane >> 3, lr = lane & 7;
    const uint32_t lof = (uint32_t)(((ls & 1) * 8 + lr) * 144 + (ls >> 1) * 16);
    const uint32_t aBaseW = (uint32_t)(wr << 5) * 144u;   // warp A row base (bytes)
    const uint32_t bBaseW = (uint32_t)(wc << 6) * 144u;   // warp B row base (bytes)

    float acc[2][8][4];
#pragma unroll
    for (int i = 0; i < 2; ++i)
#pragma unroll
        for (int j = 0; j < 8; ++j)
#pragma unroll
            for (int e = 0; e < 4; ++e) acc[i][j][e] = 0.f;

#pragma unroll
    for (int it = 0; it < 4; ++it) {
        cpa16(sBase + soff + it * 32 * 36 * 4, ApG + (size_t)(it * 32) * K);
        cpa16(sBase + 18432u + soff + it * 32 * 36 * 4, BpG + (size_t)(it * 32) * K);
    }
    asm volatile("cp.async.commit_group;" ::: "memory");

    constexpr int nc = K >> 5;
    for (int c = 0; c < nc; ++c) {
        if (c + 1 < nc) {
            const int kc = (c + 1) << 5;
            const uint32_t st = sBase + (uint32_t)((c + 1) & 1) * 36864u;
#pragma unroll
            for (int it = 0; it < 4; ++it) {
                cpa16(st + soff + it * 32 * 36 * 4, ApG + (size_t)(it * 32) * K + kc);
                cpa16(st + 18432u + soff + it * 32 * 36 * 4, BpG + (size_t)(it * 32) * K + kc);
            }
            asm volatile("cp.async.commit_group;" ::: "memory");
            asm volatile("cp.async.wait_group 1;" ::: "memory");
        } else {
            asm volatile("cp.async.wait_group 0;" ::: "memory");
        }
        __syncthreads();

        const uint32_t Abase = sBase + (uint32_t)(c & 1) * 36864u + aBaseW + lof;
        const uint32_t Bbase = sBase + (uint32_t)(c & 1) * 36864u + 18432u + bBaseW + lof;
#pragma unroll
        for (int ks = 0; ks < 4; ++ks) {
            const uint32_t kbB = (uint32_t)ks * 32u;
            uint32_t af[2][4];
            ldsm4(af[0], Abase + kbB);
            ldsm4(af[1], Abase + 2304u + kbB);
#pragma unroll
            for (int jg = 0; jg < 4; ++jg) {
                uint32_t bg[4];
                ldsm4(bg, Bbase + (uint32_t)jg * 2304u + kbB);
                uint32_t bf0[2] = {bg[0], bg[2]};   // nt = 2*jg
                uint32_t bf1[2] = {bg[1], bg[3]};   // nt = 2*jg+1
                mma8(acc[0][jg * 2], af[0], bf0);
                mma8(acc[1][jg * 2], af[1], bf0);
                mma8(acc[0][jg * 2 + 1], af[0], bf1);
                mma8(acc[1][jg * 2 + 1], af[1], bf1);
            }
        }
        __syncthreads();
    }

#pragma unroll
    for (int mt = 0; mt < 2; ++mt) {
#pragma unroll
        for (int nt = 0; nt < 8; ++nt) {
            int row0 = bm + (wr << 5) + mt * 16 + g;
            int col  = bn + (wc << 6) + nt * 8 + q * 2;
            float v00 = acc[mt][nt][0], v01 = acc[mt][nt][1];
            float v10 = acc[mt][nt][2], v11 = acc[mt][nt][3];
            if (EPI == 2 || EPI == 3) {
                float2 bb = *(const float2*)(BIAS + col);
                v00 += bb.x; v01 += bb.y; v10 += bb.x; v11 += bb.y;
            }
            if (EPI == 1 || EPI == 3) {
                float2 r0 = *(const float2*)(RES + (size_t)row0 * N + col);
                float2 r1 = *(const float2*)(RES + (size_t)(row0 + 8) * N + col);
                v00 += r0.x; v01 += r0.y; v10 += r1.x; v11 += r1.y;
            }
            if (EPI == 2) {
                v00 = rndt(v00 * normcdff(v00)); v01 = rndt(v01 * normcdff(v01));
                v10 = rndt(v10 * normcdff(v10)); v11 = rndt(v11 * normcdff(v11));
            }
            *(float2*)(C + (size_t)row0 * N + col)       = make_float2(v00, v01);
            *(float2*)(C + (size_t)(row0 + 8) * N + col) = make_float2(v10, v11);
        }
    }
}

// -------- windowed attention via mma.sync (R14, unchanged) ---------------
#define ATTN_SMEM 96288
__global__ void __launch_bounds__(256) k_attn(const float* __restrict__ rpb)
{
    extern __shared__ float sa[];
    float* sQ  = sa;            // [lh*2304 + t*36 + d]
    float* sK  = sa + 4608;     // [lh*2304 + t*36 + d]
    float* sVt = sa + 9216;     // [lh*2176 + d*68 + t]
    float* sP  = sa + 13568;    // [lh*4352 + r*68 + c]
    float* srpb = sa + 22272;   // [1800]

    const int tid = threadIdx.x, lane = tid & 31, wid = tid >> 5;
    const int g = lane >> 2, q = lane & 3;
    const int hh = wid >> 2, slice = (wid & 3) << 4;
    const size_t tokbase = (size_t)blockIdx.x * 64;
    const float* qkv = g_scratch + OFF_QKV;
    float* outp = g_scratch + OFF_ATTNO;
    for (int i = tid; i < 1800; i += 256) srpb[i] = rpb[i];
    const float sc = 0.17677669529663687f;

    for (int h = 0; h < 8; h += 2) {
        __syncthreads();
#pragma unroll
        for (int m = 0; m < 4; ++m) {
            int e = m * 256 + tid;
            int t = e >> 4, rem = e & 15;
            int lh = rem >> 3, d4 = (rem & 7) << 2;
            const float* src = qkv + (tokbase + t) * 768 + (h + lh) * 32 + d4;
            float4 q4 = *(const float4*)src;
            float4 k4 = *(const float4*)(src + 256);
            float4 v4 = *(const float4*)(src + 512);
            float* dq = sQ + lh * 2304 + t * 36 + d4;
            dq[0] = rndt(q4.x * sc); dq[1] = rndt(q4.y * sc);
            dq[2] = rndt(q4.z * sc); dq[3] = rndt(q4.w * sc);
            float* dk = sK + lh * 2304 + t * 36 + d4;
            dk[0] = rndt(k4.x); dk[1] = rndt(k4.y);
            dk[2] = rndt(k4.z); dk[3] = rndt(k4.w);
            float* dv = sVt + lh * 2176 + t;
            dv[(d4 + 0) * 68] = rndt(v4.x); dv[(d4 + 1) * 68] = rndt(v4.y);
            dv[(d4 + 2) * 68] = rndt(v4.z); dv[(d4 + 3) * 68] = rndt(v4.w);
        }
        __syncthreads();

        const float* Q = sQ + hh * 2304;
        const float* K = sK + hh * 2304;
        float accs[8][4];
#pragma unroll
        for (int nt = 0; nt < 8; ++nt)
#pragma unroll
            for (int e = 0; e < 4; ++e) accs[nt][e] = 0.f;
#pragma unroll
        for (int kt = 0; kt < 4; ++kt) {
            const int kb = kt << 3;
            uint32_t af[4];
            af[0] = __float_as_uint(Q[(slice + g) * 36 + kb + q]);
            af[1] = __float_as_uint(Q[(slice + 8 + g) * 36 + kb + q]);
            af[2] = __float_as_uint(Q[(slice + g) * 36 + kb + 4 + q]);
            af[3] = __float_as_uint(Q[(slice + 8 + g) * 36 + kb + 4 + q]);
#pragma unroll
            for (int nt = 0; nt < 8; ++nt) {
                uint32_t bf[2];
                bf[0] = __float_as_uint(K[(nt * 8 + g) * 36 + kb + q]);
                bf[1] = __float_as_uint(K[(nt * 8 + g) * 36 + kb + 4 + q]);
                mma8(accs[nt], af, bf);
            }
        }

        const int r0 = slice + g, r1 = r0 + 8;
        const int ri0 = r0 >> 3, rj0 = r0 & 7, ri1 = r1 >> 3, rj1 = r1 & 7;
#pragma unroll
        for (int nt = 0; nt < 8; ++nt) {
            int c0 = nt * 8 + 2 * q, c1 = c0 + 1;
            int ci0 = c0 >> 3, cj0 = c0 & 7, ci1 = c1 >> 3, cj1 = c1 & 7;
            accs[nt][0] += srpb[((ri0 - ci0 + 7) * 15 + (rj0 - cj0 + 7)) * 8 + h + hh];
            accs[nt][1] += srpb[((ri0 - ci1 + 7) * 15 + (rj0 - cj1 + 7)) * 8 + h + hh];
            accs[nt][2] += srpb[((ri1 - ci0 + 7) * 15 + (rj1 - cj0 + 7)) * 8 + h + hh];
            accs[nt][3] += srpb[((ri1 - ci1 + 7) * 15 + (rj1 - cj1 + 7)) * 8 + h + hh];
        }

        float mx0 = accs[0][0], mx1 = accs[0][2];
#pragma unroll
        for (int nt = 0; nt < 8; ++nt) {
            mx0 = fmaxf(mx0, fmaxf(accs[nt][0], accs[nt][1]));
            mx1 = fmaxf(mx1, fmaxf(accs[nt][2], accs[nt][3]));
        }
        mx0 = fmaxf(mx0, __shfl_xor_sync(~0u, mx0, 1));
        mx0 = fmaxf(mx0, __shfl_xor_sync(~0u, mx0, 2));
        mx1 = fmaxf(mx1, __shfl_xor_sync(~0u, mx1, 1));
        mx1 = fmaxf(mx1, __shfl_xor_sync(~0u, mx1, 2));
        float sum0 = 0.f, sum1 = 0.f;
#pragma unroll
        for (int nt = 0; nt < 8; ++nt) {
            accs[nt][0] = __expf(accs[nt][0] - mx0); sum0 += accs[nt][0];
            accs[nt][1] = __expf(accs[nt][1] - mx0); sum0 += accs[nt][1];
            accs[nt][2] = __expf(accs[nt][2] - mx1); sum1 += accs[nt][2];
            accs[nt][3] = __expf(accs[nt][3] - mx1); sum1 += accs[nt][3];
        }
        sum0 += __shfl_xor_sync(~0u, sum0, 1); sum0 += __shfl_xor_sync(~0u, sum0, 2);
        sum1 += __shfl_xor_sync(~0u, sum1, 1); sum1 += __shfl_xor_sync(~0u, sum1, 2);
        float inv0 = 1.f / sum0, inv1 = 1.f / sum1;

        float* P = sP + hh * 4352;
#pragma unroll
        for (int nt = 0; nt < 8; ++nt) {
            int c0 = nt * 8 + 2 * q;
            P[r0 * 68 + c0]     = rndt(accs[nt][0] * inv0);
            P[r0 * 68 + c0 + 1] = rndt(accs[nt][1] * inv0);
            P[r1 * 68 + c0]     = rndt(accs[nt][2] * inv1);
            P[r1 * 68 + c0 + 1] = rndt(accs[nt][3] * inv1);
        }
        __syncthreads();

        const float* Vt = sVt + hh * 2176;
        float acco[4][4];
#pragma unroll
        for (int nt = 0; nt < 4; ++nt)
#pragma unroll
            for (int e = 0; e < 4; ++e) acco[nt][e] = 0.f;
#pragma unroll
        for (int kt = 0; kt < 8; ++kt) {
            const int kb = kt << 3;
            uint32_t af[4];
            af[0] = __float_as_uint(P[(slice + g) * 68 + kb + q]);
            af[1] = __float_as_uint(P[(slice + 8 + g) * 68 + kb + q]);
            af[2] = __float_as_uint(P[(slice + g) * 68 + kb + 4 + q]);
            af[3] = __float_as_uint(P[(slice + 8 + g) * 68 + kb + 4 + q]);
#pragma unroll
            for (int nt = 0; nt < 4; ++nt) {
                uint32_t bf[2];
                bf[0] = __float_as_uint(Vt[(nt * 8 + g) * 68 + kb + q]);
                bf[1] = __float_as_uint(Vt[(nt * 8 + g) * 68 + kb + 4 + q]);
                mma8(acco[nt], af, bf);
            }
        }
#pragma unroll
        for (int nt = 0; nt < 4; ++nt) {
            int col = nt * 8 + 2 * q;
            float* d0 = outp + (tokbase + r0) * 256 + (h + hh) * 32 + col;
            float* d1 = outp + (tokbase + r1) * 256 + (h + hh) * 32 + col;
            *(float2*)d0 = make_float2(rndt(acco[nt][0]), rndt(acco[nt][1]));
            *(float2*)d1 = make_float2(rndt(acco[nt][2]), rndt(acco[nt][3]));
        }
    }
}

// ---------------- host launcher ----------------
extern "C" void kernel_launch(void* const* d_in, const int* in_sizes, int n_in,
                              void* d_out, int out_size)
{
    const float* x     = (const float*)d_in[0];
    const float* ln1_g = (const float*)d_in[1];
    const float* ln1_b = (const float*)d_in[2];
    const float* ln2_g = (const float*)d_in[3];
    const float* ln2_b = (const float*)d_in[4];
    const float* w_qkv = (const float*)d_in[5];
    const float* w_out = (const float*)d_in[6];
    const float* rpb   = (const float*)d_in[7];
    const float* ln3_g = (const float*)d_in[8];
    const float* ln3_b = (const float*)d_in[9];
    const float* w1    = (const float*)d_in[10];
    const float* b1    = (const float*)d_in[11];
    const float* w2    = (const float*)d_in[12];
    const float* b2    = (const float*)d_in[13];
    float* out = (float*)d_out;

    float* S = nullptr;
    cudaGetSymbolAddress((void**)&S, g_scratch);

    cudaFuncSetAttribute(k_gemm_mma<0, 768, 256>,  cudaFuncAttributeMaxDynamicSharedMemorySize, GEMM_SMEM);
    cudaFuncSetAttribute(k_gemm_mma<1, 256, 256>,  cudaFuncAttributeMaxDynamicSharedMemorySize, GEMM_SMEM);
    cudaFuncSetAttribute(k_gemm_mma<2, 1024, 256>, cudaFuncAttributeMaxDynamicSharedMemorySize, GEMM_SMEM);
    cudaFuncSetAttribute(k_gemm_mma<3, 256, 1024>, cudaFuncAttributeMaxDynamicSharedMemorySize, GEMM_SMEM);
    cudaFuncSetAttribute(k_attn,      cudaFuncAttributeMaxDynamicSharedMemorySize, ATTN_SMEM);
    cudaFuncSetAttribute(k_gather_ln, cudaFuncAttributeMaxDynamicSharedMemorySize, GLN_SMEM);

    k_gather_ln<<<2048, 256, GLN_SMEM>>>(x, ln1_g, ln1_b, ln2_g, ln2_b);     // 1
    k_transpose<<<dim3(24, 8), 256>>>(w_qkv, S + OFF_BT_QKV, 256, 768);      // 2
    k_transpose<<<dim3(8, 8), 256>>>(w_out, S + OFF_BT_OUT, 256, 256);       // 3
    k_gemm_mma<0, 768, 256><<<dim3(6, 1024), 256, GEMM_SMEM>>>(              // 4 (profiled)
        S + OFF_T, S + OFF_BT_QKV, S + OFF_QKV, S, S);
    k_transpose<<<dim3(32, 8), 256>>>(w1, S + OFF_BT_W1, 256, 1024);         // 5
    k_transpose<<<dim3(8, 32), 256>>>(w2, S + OFF_BT_W2, 1024, 256);         // 6
    k_attn<<<2048, 256, ATTN_SMEM>>>(rpb);                                   // 7
    k_gemm_mma<1, 256, 256><<<dim3(2, 1024), 256, GEMM_SMEM>>>(
        S + OFF_ATTNO, S + OFF_BT_OUT, S + OFF_XW2, S + OFF_XW, S);
    k_ln3<<<4096, 256>>>(S + OFF_XW2, S + OFF_F, ln3_g, ln3_b);
    k_gemm_mma<2, 1024, 256><<<dim3(8, 1024), 256, GEMM_SMEM>>>(
        S + OFF_F, S + OFF_BT_W1, S + OFF_H, S, b1);
    k_gemm_mma<3, 256, 1024><<<dim3(2, 1024), 256, GEMM_SMEM>>>(
        S + OFF_H, S + OFF_BT_W2, S + OFF_T, S + OFF_XW2, b2);
    k_scatter<<<4096, 256>>>(out);
}

// round 17
// speedup vs baseline: 1.0471x; 1.0284x over previous
#include <cuda_runtime.h>
#include <cstdint>
#include <cstddef>

#define NTOK 131072
constexpr size_t NT = (size_t)NTOK;
constexpr size_t OFF_XW    = 0;
constexpr size_t OFF_T     = NT * 256;
constexpr size_t OFF_QKV   = NT * 512;
constexpr size_t OFF_ATTNO = NT * 1280;
constexpr size_t OFF_XW2   = NT * 1536;
constexpr size_t OFF_F     = NT * 1792;
constexpr size_t OFF_H     = NT * 2048;
constexpr size_t OFF_BT_QKV = NT * 3072;           // 768x256
constexpr size_t OFF_BT_OUT = OFF_BT_QKV + 196608; // 256x256
constexpr size_t OFF_BT_W1  = OFF_BT_OUT + 65536;  // 1024x256
constexpr size_t OFF_BT_W2  = OFF_BT_W1 + 262144;  // 256x1024
__device__ float g_scratch[OFF_BT_W2 + 262144];

__device__ __forceinline__ float rndt(float x) {   // round to tf32, keep as fp32
    uint32_t u; asm("cvt.rna.tf32.f32 %0, %1;" : "=r"(u) : "f"(x));
    return __uint_as_float(u);
}
__device__ __forceinline__ uint32_t smem_u32(const void* p) {
    uint32_t a;
    asm("{.reg .u64 t; cvta.to.shared.u64 t, %1; cvt.u32.u64 %0, t;}" : "=r"(a) : "l"(p));
    return a;
}
__device__ __forceinline__ void cpa16(uint32_t dst, const float* src) {
    asm volatile("cp.async.ca.shared.global [%0], [%1], 16;" :: "r"(dst), "l"(src));
}
__device__ __forceinline__ void mma8(float* d, const uint32_t* a, const uint32_t* b) {
    asm volatile(
        "mma.sync.aligned.m16n8k8.row.col.f32.tf32.tf32.f32 "
        "{%0,%1,%2,%3},{%4,%5,%6,%7},{%8,%9},{%0,%1,%2,%3};"
        : "+f"(d[0]), "+f"(d[1]), "+f"(d[2]), "+f"(d[3])
        : "r"(a[0]), "r"(a[1]), "r"(a[2]), "r"(a[3]), "r"(b[0]), "r"(b[1]));
}
// ldmatrix x4 on 32-bit data: per matrix, lane gets elem(row=lane>>2, col=lane&3)
__device__ __forceinline__ void ldsm4(uint32_t* r, uint32_t addr) {
    asm volatile("ldmatrix.sync.aligned.m8n8.x4.shared.b16 {%0,%1,%2,%3}, [%4];"
        : "=r"(r[0]), "=r"(r[1]), "=r"(r[2]), "=r"(r[3]) : "r"(addr));
}

// ---------------- weight transpose BT[n][k] = round_tf32(B[k][n]) --------
__global__ void __launch_bounds__(256) k_transpose(
    const float* __restrict__ B, float* __restrict__ BT, int K, int N)
{
    __shared__ float t[32][33];
    int kb = blockIdx.y * 32, nb = blockIdx.x * 32;
    int tx = threadIdx.x & 31, ty = threadIdx.x >> 5;
    for (int i = ty; i < 32; i += 8) t[i][tx] = B[(size_t)(kb + i) * N + nb + tx];
    __syncthreads();
    for (int i = ty; i < 32; i += 8) BT[(size_t)(nb + i) * K + kb + tx] = rndt(t[tx][i]);
}

// -------- FUSED gather + LN2(LN1(.)): one block per 8x8 window ----------
#define GLN_SMEM ((64 * 257 + 256) * 4)
__global__ void __launch_bounds__(256) k_gather_ln(
    const float* __restrict__ x,
    const float* __restrict__ g1, const float* __restrict__ b1,
    const float* __restrict__ g2, const float* __restrict__ b2)
{
    extern __shared__ float sh[];
    float* sx  = sh;                 // [64][257]
    float* st1 = sh + 64 * 257;      // [64][2]
    float* st2 = st1 + 128;          // [64][2]
    __shared__ float sg1[256], sb1[256], sg2[256], sb2[256];

    const int tid = threadIdx.x, w = blockIdx.x;
    const int b = w >> 10, wx = (w >> 5) & 31, wy = w & 31;
    sg1[tid] = g1[tid]; sb1[tid] = b1[tid];
    sg2[tid] = g2[tid]; sb2[tid] = b2[tid];

    const int tok = tid & 63, dh = tid >> 6;
    const int w1 = tok >> 3, w2 = tok & 7;
    const float* xp = x + (size_t)b * 256 * 65536 + (size_t)dh * 65536
                        + (size_t)(wx * 8 + w1) * 256 + wy * 8 + w2;
#pragma unroll
    for (int it = 0; it < 64; ++it)
        sx[tok * 257 + it * 4 + dh] = xp[(size_t)(it * 4) * 65536];
    __syncthreads();

    const int warp = tid >> 5, lane = tid & 31;
#pragma unroll
    for (int j = 0; j < 8; ++j) {
        int tk = warp * 8 + j;
        float s = 0.f, ss = 0.f;
#pragma unroll
        for (int m = 0; m < 8; ++m) {
            float v = sx[tk * 257 + lane + 32 * m]; s += v; ss += v * v;
        }
#pragma unroll
        for (int o = 16; o > 0; o >>= 1) {
            s += __shfl_xor_sync(~0u, s, o); ss += __shfl_xor_sync(~0u, ss, o);
        }
        float m1 = s * (1.f / 256.f), i1 = rsqrtf(ss * (1.f / 256.f) - m1 * m1 + 1e-5f);
        if (lane == 0) { st1[tk * 2] = m1; st1[tk * 2 + 1] = i1; }
        float s2 = 0.f, ss2 = 0.f;
#pragma unroll
        for (int m = 0; m < 8; ++m) {
            int d = lane + 32 * m;
            float u = (sx[tk * 257 + d] - m1) * i1 * sg1[d] + sb1[d];
            s2 += u; ss2 += u * u;
        }
#pragma unroll
        for (int o = 16; o > 0; o >>= 1) {
            s2 += __shfl_xor_sync(~0u, s2, o); ss2 += __shfl_xor_sync(~0u, ss2, o);
        }
        if (lane == 0) {
            float m2 = s2 * (1.f / 256.f);
            st2[tk * 2] = m2; st2[tk * 2 + 1] = rsqrtf(ss2 * (1.f / 256.f) - m2 * m2 + 1e-5f);
        }
    }
    __syncthreads();

    const size_t base = (size_t)w * 64 * 256;
    float* XW = g_scratch + OFF_XW + base;
    float* T  = g_scratch + OFF_T + base;
#pragma unroll
    for (int tk = 0; tk < 64; ++tk) {
        float v = sx[tk * 257 + tid];
        float u = (v - st1[tk * 2]) * st1[tk * 2 + 1] * sg1[tid] + sb1[tid];
        u = (u - st2[tk * 2]) * st2[tk * 2 + 1] * sg2[tid] + sb2[tid];
        XW[tk * 256 + tid] = v;
        T[tk * 256 + tid]  = rndt(u);
    }
}

// ------- single LayerNorm (ln3): reads XW2, writes F (tf32-rounded) ------
__global__ void __launch_bounds__(256) k_ln3(
    const float* __restrict__ src, float* __restrict__ dst,
    const float* __restrict__ g1, const float* __restrict__ b1)
{
    __shared__ float sm[8192], sg1[256], sb1[256], st1[32][2];
    int tid = threadIdx.x;
    size_t base = (size_t)blockIdx.x * 8192;
    sg1[tid] = g1[tid]; sb1[tid] = b1[tid];
#pragma unroll
    for (int it = 0; it < 32; ++it) sm[it * 256 + tid] = src[base + it * 256 + tid];
    __syncthreads();
    int warp = tid >> 5, lane = tid & 31;
#pragma unroll
    for (int j = 0; j < 4; ++j) {
        int tok = warp * 4 + j;
        float s = 0.f, ss = 0.f;
#pragma unroll
        for (int m = 0; m < 8; ++m) {
            float v = sm[tok * 256 + lane + 32 * m]; s += v; ss += v * v;
        }
#pragma unroll
        for (int o = 16; o > 0; o >>= 1) {
            s += __shfl_xor_sync(~0u, s, o); ss += __shfl_xor_sync(~0u, ss, o);
        }
        if (lane == 0) {
            float m1 = s * (1.f / 256.f);
            st1[tok][0] = m1;
            st1[tok][1] = rsqrtf(ss * (1.f / 256.f) - m1 * m1 + 1e-5f);
        }
    }
    __syncthreads();
#pragma unroll
    for (int tok = 0; tok < 32; ++tok) {
        float v = sm[tok * 256 + tid];
        dst[base + tok * 256 + tid] =
            rndt((v - st1[tok][0]) * st1[tok][1] * sg1[tid] + sb1[tid]);
    }
}

// -------- tf32 mma.sync GEMM with ldmatrix fragment loads ---------------
// 128x128, BK=32, 8 warps (32x64), 2-stage cp.async.ca, 2 CTAs/SM.
// EPI: 0 none | 1 +RES | 2 round(gelu(+BIAS)) | 3 +BIAS+RES
// SCAT: EPI==3 only — store directly to NCHW output (fused scatter).
#define GEMM_SMEM 73728
template <int EPI, int N, int K, int SCAT>
__global__ void __launch_bounds__(256, 2) k_gemm_mma(
    const float* __restrict__ A, const float* __restrict__ BT,
    float* __restrict__ C, const float* __restrict__ RES,
    const float* __restrict__ BIAS)
{
    extern __shared__ float smf[];   // 2 stages x (A[128][36] + B[128][36])
    const int tid = threadIdx.x, lane = tid & 31, wid = tid >> 5;
    const int bm = blockIdx.y << 7, bn = blockIdx.x << 7;
    const int wr = wid & 3, wc = wid >> 2;
    const int g = lane >> 2, q = lane & 3;

    const int lrow = tid >> 3, lkq = (tid & 7) << 2;
    const float* ApG = A  + (size_t)(bm + lrow) * K + lkq;
    const float* BpG = BT + (size_t)(bn + lrow) * K + lkq;
    const uint32_t sBase = smem_u32(smf);
    const uint32_t soff = ((uint32_t)lrow * 36 + (uint32_t)lkq) * 4;

    const int ls = lane >> 3, lr = lane & 7;
    const uint32_t lof = (uint32_t)(((ls & 1) * 8 + lr) * 144 + (ls >> 1) * 16);
    const uint32_t aBaseW = (uint32_t)(wr << 5) * 144u;
    const uint32_t bBaseW = (uint32_t)(wc << 6) * 144u;

    float acc[2][8][4];
#pragma unroll
    for (int i = 0; i < 2; ++i)
#pragma unroll
        for (int j = 0; j < 8; ++j)
#pragma unroll
            for (int e = 0; e < 4; ++e) acc[i][j][e] = 0.f;

#pragma unroll
    for (int it = 0; it < 4; ++it) {
        cpa16(sBase + soff + it * 32 * 36 * 4, ApG + (size_t)(it * 32) * K);
        cpa16(sBase + 18432u + soff + it * 32 * 36 * 4, BpG + (size_t)(it * 32) * K);
    }
    asm volatile("cp.async.commit_group;" ::: "memory");

    constexpr int nc = K >> 5;
    for (int c = 0; c < nc; ++c) {
        if (c + 1 < nc) {
            const int kc = (c + 1) << 5;
            const uint32_t st = sBase + (uint32_t)((c + 1) & 1) * 36864u;
#pragma unroll
            for (int it = 0; it < 4; ++it) {
                cpa16(st + soff + it * 32 * 36 * 4, ApG + (size_t)(it * 32) * K + kc);
                cpa16(st + 18432u + soff + it * 32 * 36 * 4, BpG + (size_t)(it * 32) * K + kc);
            }
            asm volatile("cp.async.commit_group;" ::: "memory");
            asm volatile("cp.async.wait_group 1;" ::: "memory");
        } else {
            asm volatile("cp.async.wait_group 0;" ::: "memory");
        }
        __syncthreads();

        const uint32_t Abase = sBase + (uint32_t)(c & 1) * 36864u + aBaseW + lof;
        const uint32_t Bbase = sBase + (uint32_t)(c & 1) * 36864u + 18432u + bBaseW + lof;
#pragma unroll
        for (int ks = 0; ks < 4; ++ks) {
            const uint32_t kbB = (uint32_t)ks * 32u;
            uint32_t af[2][4];
            ldsm4(af[0], Abase + kbB);
            ldsm4(af[1], Abase + 2304u + kbB);
#pragma unroll
            for (int jg = 0; jg < 4; ++jg) {
                uint32_t bg[4];
                ldsm4(bg, Bbase + (uint32_t)jg * 2304u + kbB);
                uint32_t bf0[2] = {bg[0], bg[2]};
                uint32_t bf1[2] = {bg[1], bg[3]};
                mma8(acc[0][jg * 2], af[0], bf0);
                mma8(acc[1][jg * 2], af[1], bf0);
                mma8(acc[0][jg * 2 + 1], af[0], bf1);
                mma8(acc[1][jg * 2 + 1], af[1], bf1);
            }
        }
        __syncthreads();
    }

#pragma unroll
    for (int mt = 0; mt < 2; ++mt) {
#pragma unroll
        for (int nt = 0; nt < 8; ++nt) {
            int row0 = bm + (wr << 5) + mt * 16 + g;
            int col  = bn + (wc << 6) + nt * 8 + q * 2;
            float v00 = acc[mt][nt][0], v01 = acc[mt][nt][1];
            float v10 = acc[mt][nt][2], v11 = acc[mt][nt][3];
            if (EPI == 2 || EPI == 3) {
                float2 bb = *(const float2*)(BIAS + col);
                v00 += bb.x; v01 += bb.y; v10 += bb.x; v11 += bb.y;
            }
            if (EPI == 1 || EPI == 3) {
                float2 r0 = *(const float2*)(RES + (size_t)row0 * N + col);
                float2 r1 = *(const float2*)(RES + (size_t)(row0 + 8) * N + col);
                v00 += r0.x; v01 += r0.y; v10 += r1.x; v11 += r1.y;
            }
            if (EPI == 2) {
                v00 = rndt(v00 * normcdff(v00)); v01 = rndt(v01 * normcdff(v01));
                v10 = rndt(v10 * normcdff(v10)); v11 = rndt(v11 * normcdff(v11));
            }
            if (SCAT) {
                // fused scatter: token -> NCHW.  tok = (b*1024 + wx*32 + wy)*64 + w1*8 + w2
#pragma unroll
                for (int rr = 0; rr < 2; ++rr) {
                    int tk = row0 + rr * 8;
                    float a0 = rr ? v10 : v00, a1 = rr ? v11 : v01;
                    int bb2 = tk >> 16, rem = tk & 65535;
                    int wx = rem >> 11, wy = (rem >> 6) & 31;
                    int w1 = (rem >> 3) & 7, w2 = rem & 7;
                    size_t sp = (size_t)(wx * 8 + w1) * 256 + wy * 8 + w2;
                    C[((size_t)bb2 * 256 + col) * 65536 + sp]       = a0;
                    C[((size_t)bb2 * 256 + col + 1) * 65536 + sp]   = a1;
                }
            } else {
                *(float2*)(C + (size_t)row0 * N + col)       = make_float2(v00, v01);
                *(float2*)(C + (size_t)(row0 + 8) * N + col) = make_float2(v10, v11);
            }
        }
    }
}

// -------- windowed attention via mma.sync (R14, unchanged) ---------------
#define ATTN_SMEM 96288
__global__ void __launch_bounds__(256) k_attn(const float* __restrict__ rpb)
{
    extern __shared__ float sa[];
    float* sQ  = sa;            // [lh*2304 + t*36 + d]
    float* sK  = sa + 4608;     // [lh*2304 + t*36 + d]
    float* sVt = sa + 9216;     // [lh*2176 + d*68 + t]
    float* sP  = sa + 13568;    // [lh*4352 + r*68 + c]
    float* srpb = sa + 22272;   // [1800]

    const int tid = threadIdx.x, lane = tid & 31, wid = tid >> 5;
    const int g = lane >> 2, q = lane & 3;
    const int hh = wid >> 2, slice = (wid & 3) << 4;
    const size_t tokbase = (size_t)blockIdx.x * 64;
    const float* qkv = g_scratch + OFF_QKV;
    float* outp = g_scratch + OFF_ATTNO;
    for (int i = tid; i < 1800; i += 256) srpb[i] = rpb[i];
    const float sc = 0.17677669529663687f;

    for (int h = 0; h < 8; h += 2) {
        __syncthreads();
#pragma unroll
        for (int m = 0; m < 4; ++m) {
            int e = m * 256 + tid;
            int t = e >> 4, rem = e & 15;
            int lh = rem >> 3, d4 = (rem & 7) << 2;
            const float* src = qkv + (tokbase + t) * 768 + (h + lh) * 32 + d4;
            float4 q4 = *(const float4*)src;
            float4 k4 = *(const float4*)(src + 256);
            float4 v4 = *(const float4*)(src + 512);
            float* dq = sQ + lh * 2304 + t * 36 + d4;
            dq[0] = rndt(q4.x * sc); dq[1] = rndt(q4.y * sc);
            dq[2] = rndt(q4.z * sc); dq[3] = rndt(q4.w * sc);
            float* dk = sK + lh * 2304 + t * 36 + d4;
            dk[0] = rndt(k4.x); dk[1] = rndt(k4.y);
            dk[2] = rndt(k4.z); dk[3] = rndt(k4.w);
            float* dv = sVt + lh * 2176 + t;
            dv[(d4 + 0) * 68] = rndt(v4.x); dv[(d4 + 1) * 68] = rndt(v4.y);
            dv[(d4 + 2) * 68] = rndt(v4.z); dv[(d4 + 3) * 68] = rndt(v4.w);
        }
        __syncthreads();

        const float* Q = sQ + hh * 2304;
        const float* K = sK + hh * 2304;
        float accs[8][4];
#pragma unroll
        for (int nt = 0; nt < 8; ++nt)
#pragma unroll
            for (int e = 0; e < 4; ++e) accs[nt][e] = 0.f;
#pragma unroll
        for (int kt = 0; kt < 4; ++kt) {
            const int kb = kt << 3;
            uint32_t af[4];
            af[0] = __float_as_uint(Q[(slice + g) * 36 + kb + q]);
            af[1] = __float_as_uint(Q[(slice + 8 + g) * 36 + kb + q]);
            af[2] = __float_as_uint(Q[(slice + g) * 36 + kb + 4 + q]);
            af[3] = __float_as_uint(Q[(slice + 8 + g) * 36 + kb + 4 + q]);
#pragma unroll
            for (int nt = 0; nt < 8; ++nt) {
                uint32_t bf[2];
                bf[0] = __float_as_uint(K[(nt * 8 + g) * 36 + kb + q]);
                bf[1] = __float_as_uint(K[(nt * 8 + g) * 36 + kb + 4 + q]);
                mma8(accs[nt], af, bf);
            }
        }

        const int r0 = slice + g, r1 = r0 + 8;
        const int ri0 = r0 >> 3, rj0 = r0 & 7, ri1 = r1 >> 3, rj1 = r1 & 7;
#pragma unroll
        for (int nt = 0; nt < 8; ++nt) {
            int c0 = nt * 8 + 2 * q, c1 = c0 + 1;
            int ci0 = c0 >> 3, cj0 = c0 & 7, ci1 = c1 >> 3, cj1 = c1 & 7;
            accs[nt][0] += srpb[((ri0 - ci0 + 7) * 15 + (rj0 - cj0 + 7)) * 8 + h + hh];
            accs[nt][1] += srpb[((ri0 - ci1 + 7) * 15 + (rj0 - cj1 + 7)) * 8 + h + hh];
            accs[nt][2] += srpb[((ri1 - ci0 + 7) * 15 + (rj1 - cj0 + 7)) * 8 + h + hh];
            accs[nt][3] += srpb[((ri1 - ci1 + 7) * 15 + (rj1 - cj1 + 7)) * 8 + h + hh];
        }

        float mx0 = accs[0][0], mx1 = accs[0][2];
#pragma unroll
        for (int nt = 0; nt < 8; ++nt) {
            mx0 = fmaxf(mx0, fmaxf(accs[nt][0], accs[nt][1]));
            mx1 = fmaxf(mx1, fmaxf(accs[nt][2], accs[nt][3]));
        }
        mx0 = fmaxf(mx0, __shfl_xor_sync(~0u, mx0, 1));
        mx0 = fmaxf(mx0, __shfl_xor_sync(~0u, mx0, 2));
        mx1 = fmaxf(mx1, __shfl_xor_sync(~0u, mx1, 1));
        mx1 = fmaxf(mx1, __shfl_xor_sync(~0u, mx1, 2));
        float sum0 = 0.f, sum1 = 0.f;
#pragma unroll
        for (int nt = 0; nt < 8; ++nt) {
            accs[nt][0] = __expf(accs[nt][0] - mx0); sum0 += accs[nt][0];
            accs[nt][1] = __expf(accs[nt][1] - mx0); sum0 += accs[nt][1];
            accs[nt][2] = __expf(accs[nt][2] - mx1); sum1 += accs[nt][2];
            accs[nt][3] = __expf(accs[nt][3] - mx1); sum1 += accs[nt][3];
        }
        sum0 += __shfl_xor_sync(~0u, sum0, 1); sum0 += __shfl_xor_sync(~0u, sum0, 2);
        sum1 += __shfl_xor_sync(~0u, sum1, 1); sum1 += __shfl_xor_sync(~0u, sum1, 2);
        float inv0 = 1.f / sum0, inv1 = 1.f / sum1;

        float* P = sP + hh * 4352;
#pragma unroll
        for (int nt = 0; nt < 8; ++nt) {
            int c0 = nt * 8 + 2 * q;
            P[r0 * 68 + c0]     = rndt(accs[nt][0] * inv0);
            P[r0 * 68 + c0 + 1] = rndt(accs[nt][1] * inv0);
            P[r1 * 68 + c0]     = rndt(accs[nt][2] * inv1);
            P[r1 * 68 + c0 + 1] = rndt(accs[nt][3] * inv1);
        }
        __syncthreads();

        const float* Vt = sVt + hh * 2176;
        float acco[4][4];
#pragma unroll
        for (int nt = 0; nt < 4; ++nt)
#pragma unroll
            for (int e = 0; e < 4; ++e) acco[nt][e] = 0.f;
#pragma unroll
        for (int kt = 0; kt < 8; ++kt) {
            const int kb = kt << 3;
            uint32_t af[4];
            af[0] = __float_as_uint(P[(slice + g) * 68 + kb + q]);
            af[1] = __float_as_uint(P[(slice + 8 + g) * 68 + kb + q]);
            af[2] = __float_as_uint(P[(slice + g) * 68 + kb + 4 + q]);
            af[3] = __float_as_uint(P[(slice + 8 + g) * 68 + kb + 4 + q]);
#pragma unroll
            for (int nt = 0; nt < 4; ++nt) {
                uint32_t bf[2];
                bf[0] = __float_as_uint(Vt[(nt * 8 + g) * 68 + kb + q]);
                bf[1] = __float_as_uint(Vt[(nt * 8 + g) * 68 + kb + 4 + q]);
                mma8(acco[nt], af, bf);
            }
        }
#pragma unroll
        for (int nt = 0; nt < 4; ++nt) {
            int col = nt * 8 + 2 * q;
            float* d0 = outp + (tokbase + r0) * 256 + (h + hh) * 32 + col;
            float* d1 = outp + (tokbase + r1) * 256 + (h + hh) * 32 + col;
            *(float2*)d0 = make_float2(rndt(acco[nt][0]), rndt(acco[nt][1]));
            *(float2*)d1 = make_float2(rndt(acco[nt][2]), rndt(acco[nt][3]));
        }
    }
}

// ---------------- host launcher ----------------
extern "C" void kernel_launch(void* const* d_in, const int* in_sizes, int n_in,
                              void* d_out, int out_size)
{
    const float* x     = (const float*)d_in[0];
    const float* ln1_g = (const float*)d_in[1];
    const float* ln1_b = (const float*)d_in[2];
    const float* ln2_g = (const float*)d_in[3];
    const float* ln2_b = (const float*)d_in[4];
    const float* w_qkv = (const float*)d_in[5];
    const float* w_out = (const float*)d_in[6];
    const float* rpb   = (const float*)d_in[7];
    const float* ln3_g = (const float*)d_in[8];
    const float* ln3_b = (const float*)d_in[9];
    const float* w1    = (const float*)d_in[10];
    const float* b1    = (const float*)d_in[11];
    const float* w2    = (const float*)d_in[12];
    const float* b2    = (const float*)d_in[13];
    float* out = (float*)d_out;

    float* S = nullptr;
    cudaGetSymbolAddress((void**)&S, g_scratch);

    cudaFuncSetAttribute(k_gemm_mma<0, 768, 256, 0>,  cudaFuncAttributeMaxDynamicSharedMemorySize, GEMM_SMEM);
    cudaFuncSetAttribute(k_gemm_mma<1, 256, 256, 0>,  cudaFuncAttributeMaxDynamicSharedMemorySize, GEMM_SMEM);
    cudaFuncSetAttribute(k_gemm_mma<2, 1024, 256, 0>, cudaFuncAttributeMaxDynamicSharedMemorySize, GEMM_SMEM);
    cudaFuncSetAttribute(k_gemm_mma<3, 256, 1024, 1>, cudaFuncAttributeMaxDynamicSharedMemorySize, GEMM_SMEM);
    cudaFuncSetAttribute(k_attn,      cudaFuncAttributeMaxDynamicSharedMemorySize, ATTN_SMEM);
    cudaFuncSetAttribute(k_gather_ln, cudaFuncAttributeMaxDynamicSharedMemorySize, GLN_SMEM);

    k_gather_ln<<<2048, 256, GLN_SMEM>>>(x, ln1_g, ln1_b, ln2_g, ln2_b);     // 1
    k_transpose<<<dim3(24, 8), 256>>>(w_qkv, S + OFF_BT_QKV, 256, 768);      // 2
    k_transpose<<<dim3(8, 8), 256>>>(w_out, S + OFF_BT_OUT, 256, 256);       // 3
    k_gemm_mma<0, 768, 256, 0><<<dim3(6, 1024), 256, GEMM_SMEM>>>(           // 4 (profiled)
        S + OFF_T, S + OFF_BT_QKV, S + OFF_QKV, S, S);
    k_transpose<<<dim3(32, 8), 256>>>(w1, S + OFF_BT_W1, 256, 1024);         // 5
    k_transpose<<<dim3(8, 32), 256>>>(w2, S + OFF_BT_W2, 1024, 256);         // 6
    k_attn<<<2048, 256, ATTN_SMEM>>>(rpb);                                   // 7
    k_gemm_mma<1, 256, 256, 0><<<dim3(2, 1024), 256, GEMM_SMEM>>>(
        S + OFF_ATTNO, S + OFF_BT_OUT, S + OFF_XW2, S + OFF_XW, S);
    k_ln3<<<4096, 256>>>(S + OFF_XW2, S + OFF_F, ln3_g, ln3_b);
    k_gemm_mma<2, 1024, 256, 0><<<dim3(8, 1024), 256, GEMM_SMEM>>>(
        S + OFF_F, S + OFF_BT_W1, S + OFF_H, S, b1);
    // FFN down-proj with FUSED residual + scatter: writes NCHW output directly
    k_gemm_mma<3, 256, 1024, 1><<<dim3(2, 1024), 256, GEMM_SMEM>>>(
        S + OFF_H, S + OFF_BT_W2, out, S + OFF_XW2, b2);
}